// round 10
// baseline (speedup 1.0000x reference)
#include <cuda_runtime.h>

#define BB 32
#define SS 128
#define KN 12
#define KC 10
#define KT 22
#define DD 200
#define D4 50
#define CC 45
#define CP 48
#define CP4 12
#define FF 1000
#define NTOK 4096

#define FEATB (NTOK / 2)                   // 2048 (2 tokens/block)
#define TR_ELEMS (FF * CP)                 // 48000
#define TR_BLOCKS ((TR_ELEMS + 127) / 128) // 375

#define GT 64                              // tokens per gemm tile
#define NTILES (NTOK / GT)                 // 64
#define GEMMB (NTILES * 5)                 // 320
#define APAD 51                            // shA pitch in float4 (204 floats)

#define GEMM_SMEM (GT * APAD * 16 + 100 * CP4 * 16)   // 52224 + 19200 = 71424

__device__ float g_feat[NTOK * DD];        // [tok, D]
__device__ float g_Wt[FF * CP];            // [k, 48] transposed+padded
__device__ float g_part[5 * NTOK * CP];    // [w, tok, 48]
__device__ int   g_cnt[NTILES];            // zero-init; reset by reducer

// ---------------------------------------------------------------------------
// Kernel 1 (R4-proven, unchanged): masked gather+mean, 2 tokens/block,
// ballot-compacted ids, reg-capped; W transpose appended to the grid.
// ---------------------------------------------------------------------------
__global__ void __launch_bounds__(128, 16)
feat_tr_kernel(const int* __restrict__ ngram_ids,
               const int* __restrict__ ngram_mask,
               const int* __restrict__ ctx_ids,
               const int* __restrict__ ctx_mask,
               const float* __restrict__ embed,
               const float* __restrict__ W) {
    if (blockIdx.x >= FEATB) {
        int idx = (blockIdx.x - FEATB) * 128 + threadIdx.x;
        if (idx < TR_ELEMS) {
            int c = idx / FF;
            int k = idx - c * FF;
            g_Wt[k * CP + c] = (c < CC) ? W[c * FF + k] : 0.0f;
        }
        return;
    }

    const int half = threadIdx.x >> 6;
    const int lane = threadIdx.x & 63;
    const int tok  = blockIdx.x * 2 + half;

    __shared__ int s_act[2][24];
    __shared__ int s_cnt[2];

    if (lane < 32) {
        int m = 0, id = 0;
        if (lane < KN) {
            id = ngram_ids[tok * KN + lane];
            m  = ngram_mask[tok * KN + lane];
        } else if (lane < KT) {
            id = ctx_ids[tok * KC + lane - KN];
            m  = ctx_mask[tok * KC + lane - KN];
        }
        unsigned bal = __ballot_sync(0xffffffffu, m != 0);
        if (m) s_act[half][__popc(bal & ((1u << lane) - 1u))] = id;
        if (lane == 0) s_cnt[half] = __popc(bal);
    }
    __syncthreads();

    if (lane >= D4) return;

    const int n = s_cnt[half];
    const int* act = s_act[half];
    const float4* e4 = (const float4*)embed;

    float ax = 0.f, ay = 0.f, az = 0.f, aw = 0.f;
    int j = 0;
    for (; j + 4 <= n; j += 4) {
        float4 a = e4[(long long)act[j + 0] * D4 + lane];
        float4 b = e4[(long long)act[j + 1] * D4 + lane];
        float4 c = e4[(long long)act[j + 2] * D4 + lane];
        float4 d = e4[(long long)act[j + 3] * D4 + lane];
        ax += (a.x + b.x) + (c.x + d.x);
        ay += (a.y + b.y) + (c.y + d.y);
        az += (a.z + b.z) + (c.z + d.z);
        aw += (a.w + b.w) + (c.w + d.w);
    }
    for (; j < n; j++) {
        float4 a = e4[(long long)act[j] * D4 + lane];
        ax += a.x; ay += a.y; az += a.z; aw += a.w;
    }

    float inv = 1.0f / (float)(n > 0 ? n : 1);
    float4 r; r.x = ax * inv; r.y = ay * inv; r.z = az * inv; r.w = aw * inv;
    ((float4*)g_feat)[tok * D4 + lane] = r;
}

// ---------------------------------------------------------------------------
// Kernel 2: per-window partial GEMM, 4 tokens x 4 c per thread (16 acc),
// fused last-block reduction. Grid 320 = 64 tiles x 5 w, 192 threads,
// 71.4 KB dynamic smem (3 CTAs/SM, single wave).
// Per dq-step: 4 A-LDS.128 + 4 B-LDS.128 per 64 FFMA.
// ---------------------------------------------------------------------------
__global__ void __launch_bounds__(192, 3)
gemm_kernel(const float* __restrict__ bias,
            float* __restrict__ out) {
    extern __shared__ float4 dyn[];
    float4* shA = dyn;                       // GT*APAD float4
    float4* shB = dyn + GT * APAD;           // 100*CP4 float4
    __shared__ int s_last;

    const int q = blockIdx.x;
    const int tile = q / 5;
    const int w = q - tile * 5;
    const int tokBase = tile * GT;
    const int b  = tokBase / SS;
    const int s0 = tokBase % SS;

    const int tid = threadIdx.x;
    const int tg = tid & 15;                 // tokens tg, +16, +32, +48
    const int cg = tid >> 4;                 // 0..11

    // stage A rows s0+w-2 .. s0+w+61 (zero halo)
    const float4* gf4 = (const float4*)g_feat;
    for (int i = tid; i < GT * D4; i += 192) {
        int r  = i / D4;
        int dv = i - r * D4;
        int s  = s0 + w - 2 + r;
        float4 v = make_float4(0.f, 0.f, 0.f, 0.f);
        if (s >= 0 && s < SS) v = gf4[(b * SS + s) * D4 + dv];
        shA[r * APAD + dv] = v;
    }

    float p00 = 0.f, p01 = 0.f, p02 = 0.f, p03 = 0.f;
    float p10 = 0.f, p11 = 0.f, p12 = 0.f, p13 = 0.f;
    float p20 = 0.f, p21 = 0.f, p22 = 0.f, p23 = 0.f;
    float p30 = 0.f, p31 = 0.f, p32 = 0.f, p33 = 0.f;
    const float4* Wt4 = (const float4*)g_Wt;

    #pragma unroll
    for (int h = 0; h < 2; h++) {
        __syncthreads();
        for (int i = tid; i < 100 * CP4; i += 192)
            shB[i] = Wt4[(w * DD + h * 100) * CP4 + i];
        __syncthreads();

        const float4* aR0 = &shA[(tg +  0) * APAD + h * 25];
        const float4* aR1 = &shA[(tg + 16) * APAD + h * 25];
        const float4* aR2 = &shA[(tg + 32) * APAD + h * 25];
        const float4* aR3 = &shA[(tg + 48) * APAD + h * 25];
        #pragma unroll
        for (int dq = 0; dq < 25; dq++) {
            float4 a0 = aR0[dq];
            float4 a1 = aR1[dq];
            float4 a2 = aR2[dq];
            float4 a3 = aR3[dq];
            float4 b0 = shB[(dq * 4 + 0) * CP4 + cg];
            float4 b1 = shB[(dq * 4 + 1) * CP4 + cg];
            float4 b2 = shB[(dq * 4 + 2) * CP4 + cg];
            float4 b3 = shB[(dq * 4 + 3) * CP4 + cg];

            p00 = fmaf(a0.x, b0.x, p00); p01 = fmaf(a0.x, b0.y, p01);
            p02 = fmaf(a0.x, b0.z, p02); p03 = fmaf(a0.x, b0.w, p03);
            p10 = fmaf(a1.x, b0.x, p10); p11 = fmaf(a1.x, b0.y, p11);
            p12 = fmaf(a1.x, b0.z, p12); p13 = fmaf(a1.x, b0.w, p13);
            p20 = fmaf(a2.x, b0.x, p20); p21 = fmaf(a2.x, b0.y, p21);
            p22 = fmaf(a2.x, b0.z, p22); p23 = fmaf(a2.x, b0.w, p23);
            p30 = fmaf(a3.x, b0.x, p30); p31 = fmaf(a3.x, b0.y, p31);
            p32 = fmaf(a3.x, b0.z, p32); p33 = fmaf(a3.x, b0.w, p33);

            p00 = fmaf(a0.y, b1.x, p00); p01 = fmaf(a0.y, b1.y, p01);
            p02 = fmaf(a0.y, b1.z, p02); p03 = fmaf(a0.y, b1.w, p03);
            p10 = fmaf(a1.y, b1.x, p10); p11 = fmaf(a1.y, b1.y, p11);
            p12 = fmaf(a1.y, b1.z, p12); p13 = fmaf(a1.y, b1.w, p13);
            p20 = fmaf(a2.y, b1.x, p20); p21 = fmaf(a2.y, b1.y, p21);
            p22 = fmaf(a2.y, b1.z, p22); p23 = fmaf(a2.y, b1.w, p23);
            p30 = fmaf(a3.y, b1.x, p30); p31 = fmaf(a3.y, b1.y, p31);
            p32 = fmaf(a3.y, b1.z, p32); p33 = fmaf(a3.y, b1.w, p33);

            p00 = fmaf(a0.z, b2.x, p00); p01 = fmaf(a0.z, b2.y, p01);
            p02 = fmaf(a0.z, b2.z, p02); p03 = fmaf(a0.z, b2.w, p03);
            p10 = fmaf(a1.z, b2.x, p10); p11 = fmaf(a1.z, b2.y, p11);
            p12 = fmaf(a1.z, b2.z, p12); p13 = fmaf(a1.z, b2.w, p13);
            p20 = fmaf(a2.z, b2.x, p20); p21 = fmaf(a2.z, b2.y, p21);
            p22 = fmaf(a2.z, b2.z, p22); p23 = fmaf(a2.z, b2.w, p23);
            p30 = fmaf(a3.z, b2.x, p30); p31 = fmaf(a3.z, b2.y, p31);
            p32 = fmaf(a3.z, b2.z, p32); p33 = fmaf(a3.z, b2.w, p33);

            p00 = fmaf(a0.w, b3.x, p00); p01 = fmaf(a0.w, b3.y, p01);
            p02 = fmaf(a0.w, b3.z, p02); p03 = fmaf(a0.w, b3.w, p03);
            p10 = fmaf(a1.w, b3.x, p10); p11 = fmaf(a1.w, b3.y, p11);
            p12 = fmaf(a1.w, b3.z, p12); p13 = fmaf(a1.w, b3.w, p13);
            p20 = fmaf(a2.w, b3.x, p20); p21 = fmaf(a2.w, b3.y, p21);
            p22 = fmaf(a2.w, b3.z, p22); p23 = fmaf(a2.w, b3.w, p23);
            p30 = fmaf(a3.w, b3.x, p30); p31 = fmaf(a3.w, b3.y, p31);
            p32 = fmaf(a3.w, b3.z, p32); p33 = fmaf(a3.w, b3.w, p33);
        }
    }

    // write partials (4 tokens per thread)
    float4* part4 = (float4*)g_part;
    {
        float4 v;
        v.x = p00; v.y = p01; v.z = p02; v.w = p03;
        part4[((long long)w * NTOK + tokBase + tg +  0) * CP4 + cg] = v;
        v.x = p10; v.y = p11; v.z = p12; v.w = p13;
        part4[((long long)w * NTOK + tokBase + tg + 16) * CP4 + cg] = v;
        v.x = p20; v.y = p21; v.z = p22; v.w = p23;
        part4[((long long)w * NTOK + tokBase + tg + 32) * CP4 + cg] = v;
        v.x = p30; v.y = p31; v.z = p32; v.w = p33;
        part4[((long long)w * NTOK + tokBase + tg + 48) * CP4 + cg] = v;
    }

    // last-block-of-tile reduction (fixed w-order sum -> deterministic)
    __threadfence();
    __syncthreads();
    if (tid == 0) {
        int old = atomicAdd(&g_cnt[tile], 1);
        s_last = (old == 4);
    }
    __syncthreads();
    if (!s_last) return;
    __threadfence();

    #pragma unroll
    for (int qt = 0; qt < 4; qt++) {
        int tok = tokBase + tg + qt * 16;
        float4 s = make_float4(0.f, 0.f, 0.f, 0.f);
        #pragma unroll
        for (int w2 = 0; w2 < 5; w2++) {
            float4 p = part4[((long long)w2 * NTOK + tok) * CP4 + cg];
            s.x += p.x; s.y += p.y; s.z += p.z; s.w += p.w;
        }
        int c0 = cg * 4;
        float* o = out + (long long)tok * CC;
        o[c0] = s.x + bias[c0];
        if (c0 + 1 < CC) o[c0 + 1] = s.y + bias[c0 + 1];
        if (c0 + 2 < CC) o[c0 + 2] = s.z + bias[c0 + 2];
        if (c0 + 3 < CC) o[c0 + 3] = s.w + bias[c0 + 3];
    }
    if (tid == 0) g_cnt[tile] = 0;           // reset for next graph replay
}

// ---------------------------------------------------------------------------
extern "C" void kernel_launch(void* const* d_in, const int* in_sizes, int n_in,
                              void* d_out, int out_size) {
    const int*   ngram_ids  = (const int*)d_in[0];
    const int*   ngram_mask = (const int*)d_in[1];
    const int*   ctx_ids    = (const int*)d_in[2];
    const int*   ctx_mask   = (const int*)d_in[3];
    const float* embed      = (const float*)d_in[4];
    const float* W          = (const float*)d_in[5];
    const float* bias       = (const float*)d_in[6];
    float* out = (float*)d_out;

    static bool attr_set = false;
    if (!attr_set) {
        cudaFuncSetAttribute(gemm_kernel,
                             cudaFuncAttributeMaxDynamicSharedMemorySize, GEMM_SMEM);
        attr_set = true;
    }

    feat_tr_kernel<<<FEATB + TR_BLOCKS, 128>>>(
        ngram_ids, ngram_mask, ctx_ids, ctx_mask, embed, W);
    gemm_kernel<<<GEMMB, 192, GEMM_SMEM>>>(bias, out);
}